// round 5
// baseline (speedup 1.0000x reference)
#include <cuda_runtime.h>

// out[b, i] = cos(q_weights[i]) * (sum_k sign_i(k) * x[b,k]^2) / (sum_k x[b,k]^2)
// Analytic collapse: RX^dag Z RX = cos(t) Z + sin(t) Y, and <Y> = 0 for the real
// embedded state.
//
// R5: quad-cooperative, perfectly coalesced layout. Thread i owns float4 #i of x
// (sample i/4, group i%4) -> warp LDG.128 covers exactly 4 full cache lines
// (4 wavefronts vs 16 in the per-sample layout). Quad lanes combine via
// butterfly shuffles; thread i writes the single output float out[i]
// (identity mapping -> fully coalesced STG.32).
//
// Per-group quantities (group g holds k = 4g..4g+3):
//   s  = x0^2+x1^2+x2^2+x3^2
//   p0 = (x0^2+x2^2)-(x1^2+x3^2)   (LSB-of-k sign)
//   p1 = (x0^2+x1^2)-(x2^2+x3^2)   (bit1-of-k sign)
// Quad combine:
//   norm = s0+s1+s2+s3
//   z0 = (s0+s1)-(s2+s3)   z1 = (s0-s1)+(s2-s3)   z2 = sum p1   z3 = sum p0
// 2-stage Hadamard butterfly on s yields: lane0=norm, lane1=z1, lane2=z0.

__global__ __launch_bounds__(1024) void quantum_layer_kernel(
    const float4* __restrict__ x,     // [B*4] float4
    const float*  __restrict__ qw,    // [4]
    float*        __restrict__ out,   // [B*4] floats
    int N)                            // B*4
{
    __shared__ float cq[4];
    if (threadIdx.x < 4) cq[threadIdx.x] = cosf(qw[threadIdx.x]);
    __syncthreads();

    int i = blockIdx.x * blockDim.x + threadIdx.x;
    if (i >= N) return;

    int lane = threadIdx.x & 31;
    int g = lane & 3;

    float4 v = __ldcs(x + i);
    float e0 = v.x * v.x, e1 = v.y * v.y, e2 = v.z * v.z, e3 = v.w * v.w;

    float s  = (e0 + e1) + (e2 + e3);
    float p0 = (e0 + e2) - (e1 + e3);
    float p1 = (e0 + e1) - (e2 + e3);

    const unsigned FULL = 0xffffffffu;

    // 2-stage Hadamard butterfly on s within the quad.
    float t = __shfl_xor_sync(FULL, s, 1);
    float h1 = (lane & 1) ? (t - s) : (s + t);
    t = __shfl_xor_sync(FULL, h1, 2);
    float h = (lane & 2) ? (t - h1) : (h1 + t);
    // h: lane0=norm, lane1=z1, lane2=z0, lane3=(s0-s1-s2+s3)

    // Plain quad sums of p0 and p1.
    p0 += __shfl_xor_sync(FULL, p0, 1);
    p0 += __shfl_xor_sync(FULL, p0, 2);   // = z3 everywhere
    p1 += __shfl_xor_sync(FULL, p1, 1);
    p1 += __shfl_xor_sync(FULL, p1, 2);   // = z2 everywhere

    // Move z0 (lane2) to lane0.
    float hx = __shfl_xor_sync(FULL, h, 2);   // lane0 <- z0

    // Broadcast norm from quad-lane0 to all quad lanes.
    float norm = __shfl_sync(FULL, h, lane & ~3);

    float z = (g == 0) ? hx : (g == 1) ? h : (g == 2) ? p1 : p0;

    __stcs(out + i, cq[g] * z * (1.0f / norm));
}

extern "C" void kernel_launch(void* const* d_in, const int* in_sizes, int n_in,
                              void* d_out, int out_size) {
    const float* x  = (const float*)d_in[0];
    const float* qw = (const float*)d_in[1];
    float* out = (float*)d_out;

    int N = in_sizes[0] / 4;     // B*4 float4 groups = 8388608
    int threads = 1024;
    int blocks = (N + threads - 1) / threads;   // 8192
    quantum_layer_kernel<<<blocks, threads>>>(
        (const float4*)x, qw, out, N);
}

// round 6
// speedup vs baseline: 1.6176x; 1.6176x over previous
#include <cuda_runtime.h>

// out[b, i] = cos(q_weights[i]) * (sum_k sign_i(k) * x[b,k]^2) / (sum_k x[b,k]^2)
// Analytic collapse: RX^dag Z RX = cos(t) Z + sin(t) Y, and <Y> = 0 for the real
// embedded state, so the circuit is cos(theta_i) * classical Z-expectation.
//
// R6: R4's proven body (25.57us kernel, 6.26 TB/s effective = at the streaming
// roofline) with 1024-thread blocks (2048 blocks: continues the monotone
// fewer-blocks-is-faster trend) and no bounds check (B = 2048*1024 exactly;
// launch config asserts divisibility).

__global__ __launch_bounds__(1024) void quantum_layer_kernel(
    const float4* __restrict__ x,     // [B*4] float4 = [B,16] floats
    const float*  __restrict__ qw,    // [4]
    float4*       __restrict__ out)   // [B] float4 = [B,4] floats
{
    __shared__ float cq[4];
    if (threadIdx.x < 4) cq[threadIdx.x] = cosf(qw[threadIdx.x]);
    __syncthreads();

    int i = blockIdx.x * blockDim.x + threadIdx.x;

    const float4* p = x + (size_t)i * 4;
    float4 g0 = __ldcs(p + 0);
    float4 g1 = __ldcs(p + 1);
    float4 g2 = __ldcs(p + 2);
    float4 g3 = __ldcs(p + 3);

    float a0 = g0.x * g0.x, a1 = g0.y * g0.y, a2 = g0.z * g0.z, a3 = g0.w * g0.w;
    float b0 = g1.x * g1.x, b1 = g1.y * g1.y, b2 = g1.z * g1.z, b3 = g1.w * g1.w;
    float c0 = g2.x * g2.x, c1 = g2.y * g2.y, c2 = g2.z * g2.z, c3 = g2.w * g2.w;
    float d0 = g3.x * g3.x, d1 = g3.y * g3.y, d2 = g3.z * g3.z, d3 = g3.w * g3.w;

    float sA = a0 + a1 + a2 + a3;               // group 0 (k=0..3)
    float sB = b0 + b1 + b2 + b3;               // group 1 (k=4..7)
    float sC = c0 + c1 + c2 + c3;               // group 2 (k=8..11)
    float sD = d0 + d1 + d2 + d3;               // group 3 (k=12..15)

    float p0A = (a0 + a2) - (a1 + a3);          // LSB sign within group
    float p0B = (b0 + b2) - (b1 + b3);
    float p0C = (c0 + c2) - (c1 + c3);
    float p0D = (d0 + d2) - (d1 + d3);

    float p1A = (a0 + a1) - (a2 + a3);          // bit1 sign within group
    float p1B = (b0 + b1) - (b2 + b3);
    float p1C = (c0 + c1) - (c2 + c3);
    float p1D = (d0 + d1) - (d2 + d3);

    float norm = (sA + sB) + (sC + sD);

    float z0 = (sA + sB) - (sC + sD);           // wire 0 (MSB of k)
    float z1 = (sA - sB) + (sC - sD);           // wire 1
    float z2 = (p1A + p1B) + (p1C + p1D);       // wire 2
    float z3 = (p0A + p0B) + (p0C + p0D);       // wire 3 (LSB of k)

    float inv = 1.0f / norm;

    float4 r;
    r.x = cq[0] * z0 * inv;
    r.y = cq[1] * z1 * inv;
    r.z = cq[2] * z2 * inv;
    r.w = cq[3] * z3 * inv;
    __stcs(out + i, r);
}

// Fallback with bounds check for non-divisible sizes (not used for this shape).
__global__ __launch_bounds__(1024) void quantum_layer_kernel_guard(
    const float4* __restrict__ x,
    const float*  __restrict__ qw,
    float4*       __restrict__ out,
    int B)
{
    __shared__ float cq[4];
    if (threadIdx.x < 4) cq[threadIdx.x] = cosf(qw[threadIdx.x]);
    __syncthreads();

    int i = blockIdx.x * blockDim.x + threadIdx.x;
    if (i >= B) return;

    const float4* p = x + (size_t)i * 4;
    float4 g0 = __ldcs(p + 0);
    float4 g1 = __ldcs(p + 1);
    float4 g2 = __ldcs(p + 2);
    float4 g3 = __ldcs(p + 3);

    float a0 = g0.x * g0.x, a1 = g0.y * g0.y, a2 = g0.z * g0.z, a3 = g0.w * g0.w;
    float b0 = g1.x * g1.x, b1 = g1.y * g1.y, b2 = g1.z * g1.z, b3 = g1.w * g1.w;
    float c0 = g2.x * g2.x, c1 = g2.y * g2.y, c2 = g2.z * g2.z, c3 = g2.w * g2.w;
    float d0 = g3.x * g3.x, d1 = g3.y * g3.y, d2 = g3.z * g3.z, d3 = g3.w * g3.w;

    float sA = a0 + a1 + a2 + a3;
    float sB = b0 + b1 + b2 + b3;
    float sC = c0 + c1 + c2 + c3;
    float sD = d0 + d1 + d2 + d3;

    float p0A = (a0 + a2) - (a1 + a3);
    float p0B = (b0 + b2) - (b1 + b3);
    float p0C = (c0 + c2) - (c1 + c3);
    float p0D = (d0 + d2) - (d1 + d3);

    float p1A = (a0 + a1) - (a2 + a3);
    float p1B = (b0 + b1) - (b2 + b3);
    float p1C = (c0 + c1) - (c2 + c3);
    float p1D = (d0 + d1) - (d2 + d3);

    float norm = (sA + sB) + (sC + sD);
    float z0 = (sA + sB) - (sC + sD);
    float z1 = (sA - sB) + (sC - sD);
    float z2 = (p1A + p1B) + (p1C + p1D);
    float z3 = (p0A + p0B) + (p0C + p0D);

    float inv = 1.0f / norm;

    float4 r;
    r.x = cq[0] * z0 * inv;
    r.y = cq[1] * z1 * inv;
    r.z = cq[2] * z2 * inv;
    r.w = cq[3] * z3 * inv;
    __stcs(out + i, r);
}

extern "C" void kernel_launch(void* const* d_in, const int* in_sizes, int n_in,
                              void* d_out, int out_size) {
    const float* x  = (const float*)d_in[0];
    const float* qw = (const float*)d_in[1];
    float* out = (float*)d_out;

    int B = in_sizes[0] / 16;   // 2097152
    int threads = 1024;
    if (B % threads == 0) {
        quantum_layer_kernel<<<B / threads, threads>>>(
            (const float4*)x, qw, (float4*)out);
    } else {
        quantum_layer_kernel_guard<<<(B + threads - 1) / threads, threads>>>(
            (const float4*)x, qw, (float4*)out, B);
    }
}